// round 16
// baseline (speedup 1.0000x reference)
#include <cuda_runtime.h>
#include <cuda_bf16.h>
#include <cuda_fp16.h>
#include <cstdint>

// Problem constants (fixed by the dataset)
#define NMAX 50000
#define EMAX 800000
#define NPAD 50048   // NMAX rounded up to 128

// ---------------- scratch (static __device__ arrays; no allocations) -------
__device__ __align__(16) float g_HGXR[(size_t)NPAD * 256]; // [.. | xr]
__device__ __align__(16) float g_gat [(size_t)NPAD * 128]; // gpre = aggat @ Wgat
__device__ __align__(16) float g_x2pre[(size_t)NPAD * 128];
__device__ float g_as[NMAX];
__device__ float g_ad[NMAX];
__device__ float g_ws[128];
__device__ float g_wd[128];
__device__ int   g_cnt[NMAX];
__device__ int   g_rowptr[NMAX + 1];
__device__ int   g_cursor[NMAX];
__device__ int   g_col[EMAX];
__device__ int   g_bsum[64];
__device__ int   g_boff[64];
// pre-split bf16 hi/lo A-operands
__device__ __align__(16) __nv_bfloat16 g_Xh [(size_t)NPAD * 128], g_Xl [(size_t)NPAD * 128]; // x
__device__ __align__(16) __nv_bfloat16 g_A1h[(size_t)NPAD * 128], g_A1l[(size_t)NPAD * 128]; // agg1
__device__ __align__(16) __nv_bfloat16 g_AGh[(size_t)NPAD * 128], g_AGl[(size_t)NPAD * 128]; // alpha-agg x
__device__ __align__(16) __nv_bfloat16 g_AXh[(size_t)NPAD * 512], g_AXl[(size_t)NPAD * 512]; // [agg2|h]
__device__ __align__(16) __half g_Hf[(size_t)NPAD * 256];  // fp16 copy of h (sage2 gather payload)
__device__ __align__(16) __half g_Xf[(size_t)NPAD * 128];  // fp16 copy of x (agg gather payload)
// bf16 hi/lo transposed weights: [N][K] K-major
__device__ __align__(16) __nv_bfloat16 g_B1h[256 * 128], g_B1l[256 * 128]; // [Wgat|W1r]^T
__device__ __align__(16) __nv_bfloat16 g_B2h[128 * 128], g_B2l[128 * 128]; // W1l^T
__device__ __align__(16) __nv_bfloat16 g_B3h[256 * 512], g_B3l[256 * 512]; // [W2l;W2r]^T

// ---------------- small helpers --------------------------------------------
__device__ __forceinline__ float lrelu(float x) { return x > 0.f ? x : 0.2f * x; }
__device__ __forceinline__ float4 f4zero() { return make_float4(0.f, 0.f, 0.f, 0.f); }
__device__ __forceinline__ float4 f4scale(float4 a, float s) {
    return make_float4(a.x * s, a.y * s, a.z * s, a.w * s);
}
__device__ __forceinline__ uint32_t smem_u32(const void* p) {
    uint32_t a;
    asm("{ .reg .u64 t; cvta.to.shared.u64 t, %1; cvt.u32.u64 %0, t; }" : "=r"(a) : "l"(p));
    return a;
}
__device__ __forceinline__ uint32_t swz(uint32_t off) { return off ^ ((off >> 3) & 0x70); }

__device__ __forceinline__ void split2(float a, float b, uint32_t& hi, uint32_t& lo) {
    __nv_bfloat16 h0 = __float2bfloat16(a), h1 = __float2bfloat16(b);
    float r0 = a - __bfloat162float(h0), r1 = b - __bfloat162float(h1);
    __nv_bfloat16 l0 = __float2bfloat16(r0), l1 = __float2bfloat16(r1);
    hi = ((uint32_t)__bfloat16_as_ushort(h1) << 16) | __bfloat16_as_ushort(h0);
    lo = ((uint32_t)__bfloat16_as_ushort(l1) << 16) | __bfloat16_as_ushort(l0);
}
__device__ __forceinline__ float bflo(uint32_t u) { return __uint_as_float(u << 16); }
__device__ __forceinline__ float bfhi(uint32_t u) { return __uint_as_float(u & 0xFFFF0000u); }

// ---------------- warp MMA primitives (sm_80+, legal on plain sm_103) -------
__device__ __forceinline__ void ldsm4(uint32_t* r, uint32_t addr) {
    asm volatile("ldmatrix.sync.aligned.m8n8.x4.shared.b16 {%0,%1,%2,%3}, [%4];"
                 : "=r"(r[0]), "=r"(r[1]), "=r"(r[2]), "=r"(r[3]) : "r"(addr));
}
__device__ __forceinline__ void mma16816(float* d, const uint32_t* a, const uint32_t* b) {
    asm volatile(
        "mma.sync.aligned.m16n8k16.row.col.f32.bf16.bf16.f32 "
        "{%0,%1,%2,%3}, {%4,%5,%6,%7}, {%8,%9}, {%0,%1,%2,%3};"
        : "+f"(d[0]), "+f"(d[1]), "+f"(d[2]), "+f"(d[3])
        : "r"(a[0]), "r"(a[1]), "r"(a[2]), "r"(a[3]), "r"(b[0]), "r"(b[1]));
}
__device__ __forceinline__ void cpa16(uint32_t saddr, const void* gaddr) {
    asm volatile("cp.async.cg.shared.global [%0], [%1], 16;" :: "r"(saddr), "l"(gaddr));
}
__device__ __forceinline__ void cpa_commit() { asm volatile("cp.async.commit_group;"); }
__device__ __forceinline__ void cpa_wait0() { asm volatile("cp.async.wait_group 0;"); }

// ---------------- weight packing: transpose + bf16 hi/lo split ---------------
__device__ __forceinline__ void wsplit(float w, __nv_bfloat16& h, __nv_bfloat16& l) {
    h = __float2bfloat16(w);
    l = __float2bfloat16(w - __bfloat162float(h));
}

__global__ void k_buildW(const float* __restrict__ Wg, const float* __restrict__ W1r,
                         const float* __restrict__ W1l, const float* __restrict__ W2l,
                         const float* __restrict__ W2r) {
    int i = blockIdx.x * blockDim.x + threadIdx.x;
    if (i < 256 * 128) {
        int nn = i / 128, k = i % 128;
        float w = (nn < 128) ? Wg[k * 128 + nn] : W1r[k * 128 + (nn - 128)];
        wsplit(w, g_B1h[i], g_B1l[i]);
    }
    if (i < 128 * 128) {
        int nn = i / 128, k = i % 128;
        wsplit(W1l[k * 128 + nn], g_B2h[i], g_B2l[i]);
    }
    if (i < 256 * 512) {
        int nn = i / 512, k = i % 512;
        float w = (k < 256) ? W2l[k * 256 + nn] : W2r[(k - 256) * 256 + nn];
        wsplit(w, g_B3h[i], g_B3l[i]);
    }
}

// ---------------- ws = Wgat @ att_s, wd = Wgat @ att_d (warp per output) ----
__global__ void k_prew(const float* __restrict__ Wg, const float* __restrict__ att_s,
                       const float* __restrict__ att_d) {
    int k = (blockIdx.x * blockDim.x + threadIdx.x) >> 5;
    int lane = threadIdx.x & 31;
    if (k >= 128) return;
    float4 w = ((const float4*)(Wg + k * 128))[lane];
    float4 a = ((const float4*)att_s)[lane];
    float4 d = ((const float4*)att_d)[lane];
    float s = w.x * a.x + w.y * a.y + w.z * a.z + w.w * a.w;
    float t = w.x * d.x + w.y * d.y + w.z * d.z + w.w * d.w;
    for (int o = 16; o; o >>= 1) {
        s += __shfl_xor_sync(0xffffffffu, s, o);
        t += __shfl_xor_sync(0xffffffffu, t, o);
    }
    if (lane == 0) { g_ws[k] = s; g_wd[k] = t; }
}

// ---------------- split x into bf16 hi/lo + fp16 copy + attention scalars ---
__global__ void k_splitX(const float* __restrict__ x, int n) {
    int i = blockIdx.x * blockDim.x + threadIdx.x;   // float4 index over NPAD*32
    if (i >= NPAD * 32) return;
    int row = i >> 5;
    int lane = i & 31;
    float4 v = (row < n) ? ((const float4*)x)[i] : f4zero();
    uint32_t hx, lx, hz, lz;
    split2(v.x, v.y, hx, lx);
    split2(v.z, v.w, hz, lz);
    ((uint2*)g_Xh)[i] = make_uint2(hx, hz);
    ((uint2*)g_Xl)[i] = make_uint2(lx, lz);
    // fp16 copy for agg gather
    __half2 f0 = __floats2half2_rn(v.x, v.y);
    __half2 f1 = __floats2half2_rn(v.z, v.w);
    ((uint2*)g_Xf)[i] = make_uint2(*(uint32_t*)&f0, *(uint32_t*)&f1);
    float4 a = ((const float4*)g_ws)[lane];
    float4 d = ((const float4*)g_wd)[lane];
    float s = v.x * a.x + v.y * a.y + v.z * a.z + v.w * a.w;
    float t = v.x * d.x + v.y * d.y + v.z * d.z + v.w * d.w;
    for (int o = 16; o; o >>= 1) {
        s += __shfl_xor_sync(0xffffffffu, s, o);
        t += __shfl_xor_sync(0xffffffffu, t, o);
    }
    if (lane == 0 && row < n) { g_as[row] = s; g_ad[row] = t; }
}

// ---------------- CSR build --------------------------------------------------
__global__ void k_deg(const int* __restrict__ ei, int E) {
    int e = blockIdx.x * blockDim.x + threadIdx.x;
    if (e < E) atomicAdd(&g_cnt[ei[E + e]], 1);
}

__global__ void k_blockscan(int n) {   // 1024 threads/block
    __shared__ int ws[32];
    int i = blockIdx.x * 1024 + threadIdx.x;
    int lane = threadIdx.x & 31, wid = threadIdx.x >> 5;
    int v = (i < n) ? g_cnt[i] : 0;
    int x = v;
#pragma unroll
    for (int o = 1; o < 32; o <<= 1) {
        int t = __shfl_up_sync(0xffffffffu, x, o);
        if (lane >= o) x += t;
    }
    if (lane == 31) ws[wid] = x;
    __syncthreads();
    if (wid == 0) {
        int s = ws[lane];
#pragma unroll
        for (int o = 1; o < 32; o <<= 1) {
            int t = __shfl_up_sync(0xffffffffu, s, o);
            if (lane >= o) s += t;
        }
        ws[lane] = s;
    }
    __syncthreads();
    int excl = x - v + (wid ? ws[wid - 1] : 0);
    if (i < n) g_rowptr[i] = excl;
    if (threadIdx.x == 1023) g_bsum[blockIdx.x] = excl + v;
}

__global__ void k_scantop(int nb, int n) {  // 64 threads, nb <= 64
    __shared__ int sh[64];
    int t = threadIdx.x;
    int v0 = (t < nb) ? g_bsum[t] : 0;
    sh[t] = v0;
    __syncthreads();
    for (int o = 1; o < 64; o <<= 1) {
        int v = (t >= o) ? sh[t - o] : 0;
        __syncthreads();
        sh[t] += v;
        __syncthreads();
    }
    if (t < nb) g_boff[t] = sh[t] - v0;
    if (t == 0) g_rowptr[n] = sh[63];
}

__global__ void k_addoff(int n) {
    int i = blockIdx.x * blockDim.x + threadIdx.x;
    if (i < n) {
        int val = g_rowptr[i] + g_boff[i >> 10];
        g_rowptr[i] = val;
        g_cursor[i] = val;
    }
}

__global__ void k_scatter(const int* __restrict__ ei, int E) {
    int e = blockIdx.x * blockDim.x + threadIdx.x;
    if (e < E) {
        int s = ei[e];
        int d = ei[E + e];
        int p = atomicAdd(&g_cursor[d], 1);
        g_col[p] = s;
    }
}

// ---------------- merged GAT + SAGE1 aggregation over fp16 x (warp/node) ----
__global__ void k_agg(const float* __restrict__ x, int n) {
    int w = (blockIdx.x * blockDim.x + threadIdx.x) >> 5;
    int lane = threadIdx.x & 31;
    if (w >= n) return;
    int base = g_rowptr[w];
    int deg = g_rowptr[w + 1] - base;
    float adi = g_ad[w];
    float eself = lrelu(g_as[w] + adi);
    float m = eself;
    for (int j = lane; j < deg; j += 32)
        m = fmaxf(m, lrelu(g_as[g_col[base + j]] + adi));
    for (int o = 16; o; o >>= 1) m = fmaxf(m, __shfl_xor_sync(0xffffffffu, m, o));

    float wself = __expf(eself - m);
    float ssum = wself;
    // self node in full precision
    float4 xv = ((const float4*)(x + (size_t)w * 128))[lane];
    float a0 = xv.x * wself, a1 = xv.y * wself, a2 = xv.z * wself, a3 = xv.w * wself;
    float s0 = 0.f, s1 = 0.f, s2 = 0.f, s3 = 0.f;
    int c4 = lane;   // uint2 index within fp16 row (4 halves per lane)
    int j = 0;
    for (; j + 1 < deg; j += 2) {
        int n0 = g_col[base + j], n1 = g_col[base + j + 1];
        float w0 = __expf(lrelu(g_as[n0] + adi) - m);
        float w1 = __expf(lrelu(g_as[n1] + adi) - m);
        uint2 P0 = ((const uint2*)(g_Xf + (size_t)n0 * 128))[c4];
        uint2 P1 = ((const uint2*)(g_Xf + (size_t)n1 * 128))[c4];
        float2 u0 = __half22float2(*(__half2*)&P0.x);
        float2 u1 = __half22float2(*(__half2*)&P0.y);
        float2 v0 = __half22float2(*(__half2*)&P1.x);
        float2 v1 = __half22float2(*(__half2*)&P1.y);
        ssum += w0 + w1;
        a0 = fmaf(w0, u0.x, a0); a1 = fmaf(w0, u0.y, a1);
        a2 = fmaf(w0, u1.x, a2); a3 = fmaf(w0, u1.y, a3);
        a0 = fmaf(w1, v0.x, a0); a1 = fmaf(w1, v0.y, a1);
        a2 = fmaf(w1, v1.x, a2); a3 = fmaf(w1, v1.y, a3);
        s0 += u0.x + v0.x; s1 += u0.y + v0.y;
        s2 += u1.x + v1.x; s3 += u1.y + v1.y;
    }
    if (j < deg) {
        int n0 = g_col[base + j];
        float w0 = __expf(lrelu(g_as[n0] + adi) - m);
        uint2 P0 = ((const uint2*)(g_Xf + (size_t)n0 * 128))[c4];
        float2 u0 = __half22float2(*(__half2*)&P0.x);
        float2 u1 = __half22float2(*(__half2*)&P0.y);
        ssum += w0;
        a0 = fmaf(w0, u0.x, a0); a1 = fmaf(w0, u0.y, a1);
        a2 = fmaf(w0, u1.x, a2); a3 = fmaf(w0, u1.y, a3);
        s0 += u0.x; s1 += u0.y; s2 += u1.x; s3 += u1.y;
    }
    float ia = 1.f / ssum;
    float is = 1.f / fmaxf((float)deg, 1.f);
    a0 *= ia; a1 *= ia; a2 *= ia; a3 *= ia;
    s0 *= is; s1 *= is; s2 *= is; s3 *= is;
    uint32_t h0, l0, h1, l1;
    split2(a0, a1, h0, l0);
    split2(a2, a3, h1, l1);
    ((uint2*)(g_AGh + (size_t)w * 128))[lane] = make_uint2(h0, h1);
    ((uint2*)(g_AGl + (size_t)w * 128))[lane] = make_uint2(l0, l1);
    split2(s0, s1, h0, l0);
    split2(s2, s3, h1, l1);
    ((uint2*)(g_A1h + (size_t)w * 128))[lane] = make_uint2(h0, h1);
    ((uint2*)(g_A1l + (size_t)w * 128))[lane] = make_uint2(l0, l1);
}

// ---------------- bf16x3 mma.sync GEMM body, cp.async staged -----------------
template <int K, int NC, int STAGES>
__device__ __forceinline__ void mma_body(
        const __nv_bfloat16* __restrict__ Ah, const __nv_bfloat16* __restrict__ Al,
        const __nv_bfloat16* __restrict__ Bh, const __nv_bfloat16* __restrict__ Bl,
        float* __restrict__ C, int ldc, int nrows) {
    constexpr int NCH = K / 64;
    constexpr int WN = NC / 4;
    constexpr int NF = WN / 8;
    constexpr int AB = 128 * 128;
    constexpr int BB = NC * 128;
    constexpr int STAGE = 2 * AB + 2 * BB;

    extern __shared__ char dsm[];
    uint32_t raw = smem_u32(dsm);
    uint32_t base = (raw + 1023u) & ~1023u;

    int tid = threadIdx.x;
    int lane = tid & 31, wid = tid >> 5;
    int wm0 = (wid >> 2) * 64;
    int wn0 = (wid & 3) * WN;
    int row0 = blockIdx.x * 128;

    float acc[4][NF][4];
#pragma unroll
    for (int mf = 0; mf < 4; mf++)
#pragma unroll
        for (int nf = 0; nf < NF; nf++)
#pragma unroll
            for (int q = 0; q < 4; q++) acc[mf][nf][q] = 0.f;

    int srow = tid >> 1;
    int half = tid & 1;
    const char* pAh = (const char*)(Ah + (size_t)(row0 + srow) * K) + half * 64;
    const char* pAl = (const char*)(Al + (size_t)(row0 + srow) * K) + half * 64;
    uint32_t aoff = (uint32_t)srow * 128u + (uint32_t)half * 64u;

    auto issue = [&](int ch, int buf) {
        uint32_t sb = base + (uint32_t)buf * STAGE;
        int kb = ch * 128;
#pragma unroll
        for (int g = 0; g < 4; g++) {
            uint32_t so = swz(aoff + g * 16u);
            cpa16(sb + so, pAh + kb + g * 16);
            cpa16(sb + AB + so, pAl + kb + g * 16);
        }
#pragma unroll
        for (int rr = 0; rr < NC / 128; rr++) {
            int nrow = srow + rr * 128;
            const char* pbh = (const char*)(Bh + (size_t)nrow * K) + half * 64;
            const char* pbl = (const char*)(Bl + (size_t)nrow * K) + half * 64;
            uint32_t boff = (uint32_t)nrow * 128u + (uint32_t)half * 64u;
#pragma unroll
            for (int g = 0; g < 4; g++) {
                uint32_t so = swz(boff + g * 16u);
                cpa16(sb + 2 * AB + so, pbh + kb + g * 16);
                cpa16(sb + 2 * AB + BB + so, pbl + kb + g * 16);
            }
        }
        cpa_commit();
    };

    auto compute = [&](uint32_t sb) {
        uint32_t aAh = sb, aAl = sb + AB, aBh = sb + 2 * AB, aBl = sb + 2 * AB + BB;
#pragma unroll
        for (int ks = 0; ks < 4; ks++) {
            uint32_t Afh[4][4], Afl[4][4];
            uint32_t ar = (uint32_t)(wm0 + (lane & 15));
            uint32_t akb = (uint32_t)(ks * 16 + ((lane >> 4) * 8));
#pragma unroll
            for (int mf = 0; mf < 4; mf++) {
                uint32_t off = swz((ar + mf * 16) * 128u + akb * 2u);
                ldsm4(Afh[mf], aAh + off);
                ldsm4(Afl[mf], aAl + off);
            }
#pragma unroll
            for (int np = 0; np < NF / 2; np++) {
                uint32_t nr = (uint32_t)(wn0 + np * 16 + (lane & 7) + ((lane >> 4) & 1) * 8);
                uint32_t bkb = (uint32_t)(ks * 16 + ((lane >> 3) & 1) * 8);
                uint32_t off = swz(nr * 128u + bkb * 2u);
                uint32_t Bfh[4], Bfl[4];
                ldsm4(Bfh, aBh + off);
                ldsm4(Bfl, aBl + off);
#pragma unroll
                for (int mf = 0; mf < 4; mf++) {
#pragma unroll
                    for (int j = 0; j < 2; j++) {
                        float* d = acc[mf][np * 2 + j];
                        mma16816(d, Afh[mf], Bfh + j * 2);
                        mma16816(d, Afh[mf], Bfl + j * 2);
                        mma16816(d, Afl[mf], Bfh + j * 2);
                    }
                }
            }
        }
    };

    if (STAGES == 2) {
        issue(0, 0);
        for (int ch = 0; ch < NCH; ch++) {
            cpa_wait0();
            __syncthreads();
            if (ch + 1 < NCH) issue(ch + 1, (ch + 1) & 1);
            compute(base + (uint32_t)(ch & 1) * STAGE);
            __syncthreads();
        }
    } else {
        for (int ch = 0; ch < NCH; ch++) {
            issue(ch, 0);
            cpa_wait0();
            __syncthreads();
            compute(base);
            __syncthreads();
        }
    }

#pragma unroll
    for (int mf = 0; mf < 4; mf++) {
        int r_ = row0 + wm0 + mf * 16 + (lane >> 2);
#pragma unroll
        for (int nf = 0; nf < NF; nf++) {
            int c = wn0 + nf * 8 + (lane & 3) * 2;
            if (r_ < nrows)
                *(float2*)(C + (size_t)r_ * ldc + c) = make_float2(acc[mf][nf][0], acc[mf][nf][1]);
            if (r_ + 8 < nrows)
                *(float2*)(C + (size_t)(r_ + 8) * ldc + c) = make_float2(acc[mf][nf][2], acc[mf][nf][3]);
        }
    }
}

// single-stage kernel (short K; 2 CTAs/SM via launch_bounds)
template <int K, int NC>
__global__ void __launch_bounds__(256, 2)
k_mma1(const __nv_bfloat16* __restrict__ Ah, const __nv_bfloat16* __restrict__ Al,
       const __nv_bfloat16* __restrict__ Bh, const __nv_bfloat16* __restrict__ Bl,
       float* __restrict__ C, int ldc, int nrows) {
    mma_body<K, NC, 1>(Ah, Al, Bh, Bl, C, ldc, nrows);
}

// dual-operand single-stage variant: blockIdx.y selects operand set
template <int K, int NC>
__global__ void __launch_bounds__(256, 2)
k_mma1d(const __nv_bfloat16* __restrict__ Ah0, const __nv_bfloat16* __restrict__ Al0,
        const __nv_bfloat16* __restrict__ Bh0, const __nv_bfloat16* __restrict__ Bl0,
        float* __restrict__ C0,
        const __nv_bfloat16* __restrict__ Ah1, const __nv_bfloat16* __restrict__ Al1,
        const __nv_bfloat16* __restrict__ Bh1, const __nv_bfloat16* __restrict__ Bl1,
        float* __restrict__ C1, int nrows) {
    if (blockIdx.y == 0)
        mma_body<K, NC, 1>(Ah0, Al0, Bh0, Bl0, C0, NC, nrows);
    else
        mma_body<K, NC, 1>(Ah1, Al1, Bh1, Bl1, C1, NC, nrows);
}

// ---------------- G3 fused: h2pre GEMM + LN2 + classifier dot ---------------
__global__ void __launch_bounds__(256)
k_g3fused(const __nv_bfloat16* __restrict__ Ah, const __nv_bfloat16* __restrict__ Al,
          const __nv_bfloat16* __restrict__ Bh, const __nv_bfloat16* __restrict__ Bl,
          const float* __restrict__ b2l, const float* __restrict__ g2,
          const float* __restrict__ be2, const float* __restrict__ Wc,
          const float* __restrict__ bc, float* __restrict__ out, int nrows) {
    constexpr int K = 512, NC = 256;
    constexpr int NCH = K / 64;
    constexpr int NF = 8;               // WN=64
    constexpr int AB = 128 * 128;
    constexpr int BB = NC * 128;
    constexpr int STAGE = 2 * AB + 2 * BB;
    constexpr int SROW = 258;           // padded fp32 row stride

    extern __shared__ char dsm[];
    uint32_t raw = smem_u32(dsm);
    uint32_t base = (raw + 1023u) & ~1023u;

    int tid = threadIdx.x;
    int lane = tid & 31, wid = tid >> 5;
    int wm0 = (wid >> 2) * 64;
    int wn0 = (wid & 3) * 64;
    int row0 = blockIdx.x * 128;

    float acc[4][NF][4];
#pragma unroll
    for (int mf = 0; mf < 4; mf++)
#pragma unroll
        for (int nf = 0; nf < NF; nf++)
#pragma unroll
            for (int q = 0; q < 4; q++) acc[mf][nf][q] = 0.f;

    int srow = tid >> 1;
    int half = tid & 1;
    const char* pAh = (const char*)(Ah + (size_t)(row0 + srow) * K) + half * 64;
    const char* pAl = (const char*)(Al + (size_t)(row0 + srow) * K) + half * 64;
    uint32_t aoff = (uint32_t)srow * 128u + (uint32_t)half * 64u;

    auto issue = [&](int ch, int buf) {
        uint32_t sb = base + (uint32_t)buf * STAGE;
        int kb = ch * 128;
#pragma unroll
        for (int g = 0; g < 4; g++) {
            uint32_t so = swz(aoff + g * 16u);
            cpa16(sb + so, pAh + kb + g * 16);
            cpa16(sb + AB + so, pAl + kb + g * 16);
        }
#pragma unroll
        for (int rr = 0; rr < 2; rr++) {
            int nrow = srow + rr * 128;
            const char* pbh = (const char*)(Bh + (size_t)nrow * K) + half * 64;
            const char* pbl = (const char*)(Bl + (size_t)nrow * K) + half * 64;
            uint32_t boff = (uint32_t)nrow * 128u + (uint32_t)half * 64u;
#pragma unroll
            for (int g = 0; g < 4; g++) {
                uint32_t so = swz(boff + g * 16u);
                cpa16(sb + 2 * AB + so, pbh + kb + g * 16);
                cpa16(sb + 2 * AB + BB + so, pbl + kb + g * 16);
            }
        }
        cpa_commit();
    };

    auto compute = [&](uint32_t sb) {
        uint32_t aAh = sb, aAl = sb + AB, aBh = sb + 2 * AB, aBl = sb + 2 * AB + BB;
#pragma unroll
        for (int ks = 0; ks < 4; ks++) {
            uint32_t Afh[4][4], Afl[4][4];
            uint32_t ar = (uint32_t)(wm0 + (lane & 15));
            uint32_t akb = (uint32_t)(ks * 16 + ((lane >> 4) * 8));
#pragma unroll
            for (int mf = 0; mf < 4; mf++) {
                uint32_t off = swz((ar + mf * 16) * 128u + akb * 2u);
                ldsm4(Afh[mf], aAh + off);
                ldsm4(Afl[mf], aAl + off);
            }
#pragma unroll
            for (int np = 0; np < NF / 2; np++) {
                uint32_t nr = (uint32_t)(wn0 + np * 16 + (lane & 7) + ((lane >> 4) & 1) * 8);
                uint32_t bkb = (uint32_t)(ks * 16 + ((lane >> 3) & 1) * 8);
                uint32_t off = swz(nr * 128u + bkb * 2u);
                uint32_t Bfh[4], Bfl[4];
                ldsm4(Bfh, aBh + off);
                ldsm4(Bfl, aBl + off);
#pragma unroll
                for (int mf = 0; mf < 4; mf++) {
#pragma unroll
                    for (int j = 0; j < 2; j++) {
                        float* d = acc[mf][np * 2 + j];
                        mma16816(d, Afh[mf], Bfh + j * 2);
                        mma16816(d, Afh[mf], Bfl + j * 2);
                        mma16816(d, Afl[mf], Bfh + j * 2);
                    }
                }
            }
        }
    };

    issue(0, 0);
    for (int ch = 0; ch < NCH; ch++) {
        cpa_wait0();
        __syncthreads();
        if (ch + 1 < NCH) issue(ch + 1, (ch + 1) & 1);
        compute(base + (uint32_t)(ch & 1) * STAGE);
        __syncthreads();
    }

    // ---- fused epilogue: stage 128x256 tile in smem (pipeline smem is dead) ----
    float* sC = (float*)(dsm + (base - raw));
#pragma unroll
    for (int mf = 0; mf < 4; mf++) {
        int r_ = wm0 + mf * 16 + (lane >> 2);
#pragma unroll
        for (int nf = 0; nf < NF; nf++) {
            int c = wn0 + nf * 8 + (lane & 3) * 2;
            *(float2*)(sC + r_ * SROW + c) = make_float2(acc[mf][nf][0], acc[mf][nf][1]);
            *(float2*)(sC + (r_ + 8) * SROW + c) = make_float2(acc[mf][nf][2], acc[mf][nf][3]);
        }
    }
    __syncthreads();

    float bc0 = bc[0];
    for (int rr = 0; rr < 16; rr++) {
        int r = wid * 16 + rr;
        int grow = row0 + r;
        float v[8];
        float s = 0.f, q = 0.f;
#pragma unroll
        for (int t = 0; t < 8; t++) {
            int c = lane + 32 * t;
            float val = sC[r * SROW + c] + b2l[c];
            v[t] = val;
            s += val;
            q += val * val;
        }
        for (int o = 16; o; o >>= 1) {
            s += __shfl_xor_sync(0xffffffffu, s, o);
            q += __shfl_xor_sync(0xffffffffu, q, o);
        }
        float mu = s * (1.f / 256.f);
        float var = fmaxf(q * (1.f / 256.f) - mu * mu, 0.f);
        float rs = rsqrtf(var + 1e-5f);
        float a2 = 0.f;
#pragma unroll
        for (int t = 0; t < 8; t++) {
            int c = lane + 32 * t;
            float y = (v[t] - mu) * rs * g2[c] + be2[c];
            y = fmaxf(y, 0.f);
            a2 = fmaf(y, Wc[c], a2);
        }
        for (int o = 16; o; o >>= 1) a2 += __shfl_xor_sync(0xffffffffu, a2, o);
        if (lane == 0 && grow < nrows) out[grow] = a2 + bc0;
    }
}

// ---------------- LN1: h = relu(LN(...)) -> split AX[:,256:] + fp16 copy ----
__global__ void k_ln1(const float* __restrict__ bgat, const float* __restrict__ b1l,
                      const float* __restrict__ g1, const float* __restrict__ be1, int n) {
    int w = (blockIdx.x * blockDim.x + threadIdx.x) >> 5;
    int lane = threadIdx.x & 31;
    if (w >= n) return;
    float v[8];
    if (lane < 16) {
        int j0 = lane * 8;
        const float4* p = (const float4*)(g_gat + (size_t)w * 128 + j0);
        const float4* pb = (const float4*)(bgat + j0);
        float4 a = p[0], b = p[1], ab = pb[0], bb = pb[1];
        v[0] = a.x + ab.x; v[1] = a.y + ab.y; v[2] = a.z + ab.z; v[3] = a.w + ab.w;
        v[4] = b.x + bb.x; v[5] = b.y + bb.y; v[6] = b.z + bb.z; v[7] = b.w + bb.w;
    } else {
        int j0 = (lane - 16) * 8;
        const float4* p1 = (const float4*)(g_x2pre + (size_t)w * 128 + j0);
        const float4* p2 = (const float4*)(g_HGXR + (size_t)w * 256 + 128 + j0);
        const float4* pb = (const float4*)(b1l + j0);
        float4 a1 = p1[0], a2 = p2[0], ab = pb[0];
        float4 c1 = p1[1], c2 = p2[1], cb = pb[1];
        v[0] = a1.x + a2.x + ab.x; v[1] = a1.y + a2.y + ab.y;
        v[2] = a1.z + a2.z + ab.z; v[3] = a1.w + a2.w + ab.w;
        v[4] = c1.x + c2.x + cb.x; v[5] = c1.y + c2.y + cb.y;
        v[6] = c1.z + c2.z + cb.z; v[7] = c1.w + c2.w + cb.w;
    }
    float s = 0.f, q = 0.f;
#pragma unroll
    for (int t = 0; t < 8; t++) { s += v[t]; q += v[t] * v[t]; }
    for (int o = 16; o; o >>= 1) {
        s += __shfl_xor_sync(0xffffffffu, s, o);
        q += __shfl_xor_sync(0xffffffffu, q, o);
    }
    float mu = s * (1.f / 256.f);
    float var = fmaxf(q * (1.f / 256.f) - mu * mu, 0.f);
    float rs = rsqrtf(var + 1e-5f);
    int c0 = lane * 8;
    float o[8];
#pragma unroll
    for (int t = 0; t < 8; t++) {
        float y = (v[t] - mu) * rs * g1[c0 + t] + be1[c0 + t];
        o[t] = fmaxf(y, 0.f);
    }
    uint4 H, L;
    split2(o[0], o[1], H.x, L.x);
    split2(o[2], o[3], H.y, L.y);
    split2(o[4], o[5], H.z, L.z);
    split2(o[6], o[7], H.w, L.w);
    *(uint4*)(g_AXh + (size_t)w * 512 + 256 + c0) = H;
    *(uint4*)(g_AXl + (size_t)w * 512 + 256 + c0) = L;
    // fp16 copy for sage2 gather (halves its payload)
    __half2 f0 = __floats2half2_rn(o[0], o[1]);
    __half2 f1 = __floats2half2_rn(o[2], o[3]);
    __half2 f2 = __floats2half2_rn(o[4], o[5]);
    __half2 f3 = __floats2half2_rn(o[6], o[7]);
    uint4 P;
    P.x = *(uint32_t*)&f0; P.y = *(uint32_t*)&f1;
    P.z = *(uint32_t*)&f2; P.w = *(uint32_t*)&f3;
    *(uint4*)(g_Hf + (size_t)w * 256 + c0) = P;
}

// ---------------- SAGE2: mean of fp16 h -> split AX[:,0:256] ----------------
__global__ void k_sage2(int n) {
    int w = (blockIdx.x * blockDim.x + threadIdx.x) >> 5;
    int lane = threadIdx.x & 31;
    if (w >= n) return;
    int base = g_rowptr[w];
    int deg = g_rowptr[w + 1] - base;
    float acc[8];
#pragma unroll
    for (int t = 0; t < 8; t++) acc[t] = 0.f;
    int c0 = lane * 8;
    int j = 0;
    for (; j + 1 < deg; j += 2) {
        int s0 = g_col[base + j], s1 = g_col[base + j + 1];
        uint4 P0 = *(const uint4*)(g_Hf + (size_t)s0 * 256 + c0);
        uint4 P1 = *(const uint4*)(g_Hf + (size_t)s1 * 256 + c0);
        float2 f;
        f = __half22float2(*(__half2*)&P0.x); acc[0] += f.x; acc[1] += f.y;
        f = __half22float2(*(__half2*)&P0.y); acc[2] += f.x; acc[3] += f.y;
        f = __half22float2(*(__half2*)&P0.z); acc[4] += f.x; acc[5] += f.y;
        f = __half22float2(*(__half2*)&P0.w); acc[6] += f.x; acc[7] += f.y;
        f = __half22float2(*(__half2*)&P1.x); acc[0] += f.x; acc[1] += f.y;
        f = __half22float2(*(__half2*)&P1.y); acc[2] += f.x; acc[3] += f.y;
        f = __half22float2(*(__half2*)&P1.z); acc[4] += f.x; acc[5] += f.y;
        f = __half22float2(*(__half2*)&P1.w); acc[6] += f.x; acc[7] += f.y;
    }
    if (j < deg) {
        int s0 = g_col[base + j];
        uint4 P = *(const uint4*)(g_Hf + (size_t)s0 * 256 + c0);
        float2 f;
        f = __half22float2(*(__half2*)&P.x); acc[0] += f.x; acc[1] += f.y;
        f = __half22float2(*(__half2*)&P.y); acc[2] += f.x; acc[3] += f.y;
        f = __half22float2(*(__half2*)&P.z); acc[4] += f.x; acc[5] += f.y;
        f = __half22float2(*(__half2*)&P.w); acc[6] += f.x; acc[7] += f.y;
    }
    float inv = 1.f / fmaxf((float)deg, 1.f);
#pragma unroll
    for (int t = 0; t < 8; t++) acc[t] *= inv;
    uint4 H, L;
    split2(acc[0], acc[1], H.x, L.x);
    split2(acc[2], acc[3], H.y, L.y);
    split2(acc[4], acc[5], H.z, L.z);
    split2(acc[6], acc[7], H.w, L.w);
    *(uint4*)(g_AXh + (size_t)w * 512 + c0) = H;
    *(uint4*)(g_AXl + (size_t)w * 512 + c0) = L;
}

// ---------------- launch ----------------------------------------------------
extern "C" void kernel_launch(void* const* d_in, const int* in_sizes, int n_in,
                              void* d_out, int out_size) {
    const float* x      = (const float*)d_in[0];
    const int*   ei     = (const int*)d_in[1];     // int32 (JAX x64 disabled)
    const float* Wg     = (const float*)d_in[2];
    const float* att_s  = (const float*)d_in[3];
    const float* att_d  = (const float*)d_in[4];
    const float* bgat   = (const float*)d_in[5];
    const float* W1l    = (const float*)d_in[6];
    const float* b1l    = (const float*)d_in[7];
    const float* W1r    = (const float*)d_in[8];
    const float* ln1g   = (const float*)d_in[9];
    const float* ln1b   = (const float*)d_in[10];
    const float* W2l    = (const float*)d_in[11];
    const float* b2l    = (const float*)d_in[12];
    const float* W2r    = (const float*)d_in[13];
    const float* ln2g   = (const float*)d_in[14];
    const float* ln2b   = (const float*)d_in[15];
    const float* Wc     = (const float*)d_in[16];
    const float* bc     = (const float*)d_in[17];
    float* out = (float*)d_out;

    int n = in_sizes[0] / 128;
    int E = in_sizes[1] / 2;

    void *p_HGXR, *p_gat, *p_x2pre, *p_cnt;
    void *p_Xh, *p_Xl, *p_A1h, *p_A1l, *p_AGh, *p_AGl, *p_AXh, *p_AXl;
    void *p_B1h, *p_B1l, *p_B2h, *p_B2l, *p_B3h, *p_B3l;
    cudaGetSymbolAddress(&p_HGXR, g_HGXR);
    cudaGetSymbolAddress(&p_gat, g_gat);
    cudaGetSymbolAddress(&p_x2pre, g_x2pre);
    cudaGetSymbolAddress(&p_cnt, g_cnt);
    cudaGetSymbolAddress(&p_Xh, g_Xh);
    cudaGetSymbolAddress(&p_Xl, g_Xl);
    cudaGetSymbolAddress(&p_A1h, g_A1h);
    cudaGetSymbolAddress(&p_A1l, g_A1l);
    cudaGetSymbolAddress(&p_AGh, g_AGh);
    cudaGetSymbolAddress(&p_AGl, g_AGl);
    cudaGetSymbolAddress(&p_AXh, g_AXh);
    cudaGetSymbolAddress(&p_AXl, g_AXl);
    cudaGetSymbolAddress(&p_B1h, g_B1h);
    cudaGetSymbolAddress(&p_B1l, g_B1l);
    cudaGetSymbolAddress(&p_B2h, g_B2h);
    cudaGetSymbolAddress(&p_B2l, g_B2l);
    cudaGetSymbolAddress(&p_B3h, g_B3h);
    cudaGetSymbolAddress(&p_B3l, g_B3l);

    const int SMEM_G3 = 2 * (2 * 16384 + 2 * 256 * 128) + 1024;   // 197632
    const int SMEM_N128_1S = (2 * 16384 + 2 * 128 * 128) + 1024;  // 66560
    cudaFuncSetAttribute(k_mma1<128, 128>, cudaFuncAttributeMaxDynamicSharedMemorySize, SMEM_N128_1S);
    cudaFuncSetAttribute(k_mma1d<128, 128>, cudaFuncAttributeMaxDynamicSharedMemorySize, SMEM_N128_1S);
    cudaFuncSetAttribute(k_g3fused, cudaFuncAttributeMaxDynamicSharedMemorySize, SMEM_G3);

    // streams/events for capture-time DAG parallelism (created once; no device mem)
    static cudaStream_t s1 = 0, s2 = 0;
    static cudaEvent_t ev0, ev1, ev2, ev3, evbw;
    if (!s1) {
        cudaStreamCreateWithFlags(&s1, cudaStreamNonBlocking);
        cudaStreamCreateWithFlags(&s2, cudaStreamNonBlocking);
        cudaEventCreateWithFlags(&ev0, cudaEventDisableTiming);
        cudaEventCreateWithFlags(&ev1, cudaEventDisableTiming);
        cudaEventCreateWithFlags(&ev2, cudaEventDisableTiming);
        cudaEventCreateWithFlags(&ev3, cudaEventDisableTiming);
        cudaEventCreateWithFlags(&evbw, cudaEventDisableTiming);
    }

    int warpBlocks = (n + 7) / 8;       // 256 threads = 8 warps, warp-per-node
    int gemmBlocks = (n + 127) / 128;
    int nb = (n + 1023) / 1024;

    const __nv_bfloat16* BGh = (const __nv_bfloat16*)p_B1h;             // Wgat^T rows 0..127
    const __nv_bfloat16* BGl = (const __nv_bfloat16*)p_B1l;
    const __nv_bfloat16* BRh = (const __nv_bfloat16*)p_B1h + 128 * 128; // W1r^T rows 128..255
    const __nv_bfloat16* BRl = (const __nv_bfloat16*)p_B1l + 128 * 128;

    // ---- fork points ----
    cudaEventRecord(ev0, 0);

    // s1: CSR chain (depends only on ei)
    cudaStreamWaitEvent(s1, ev0, 0);
    cudaMemsetAsync(p_cnt, 0, (size_t)n * sizeof(int), s1);
    k_deg<<<(E + 255) / 256, 256, 0, s1>>>(ei, E);
    k_blockscan<<<nb, 1024, 0, s1>>>(n);
    k_scantop<<<1, 64, 0, s1>>>(nb, n);
    k_addoff<<<(n + 255) / 256, 256, 0, s1>>>(n);
    k_scatter<<<(E + 255) / 256, 256, 0, s1>>>(ei, E);
    cudaEventRecord(ev1, s1);                       // CSR done

    // s2: buildW (depends only on weights), later xr GEMM
    cudaStreamWaitEvent(s2, ev0, 0);
    k_buildW<<<512, 256, 0, s2>>>(Wg, W1r, W1l, W2l, W2r);
    cudaEventRecord(evbw, s2);                      // weights split done

    // s0: prew -> splitX (+fp16 copy, fused attn scalars)
    k_prew<<<16, 256>>>(Wg, att_s, att_d);
    k_splitX<<<(NPAD * 32 + 255) / 256, 256>>>(x, n);
    cudaEventRecord(ev2, 0);                        // splitX done

    // s2: xr = x @ W1r -> HGXR[:,128:256] (after buildW [stream order] + splitX)
    cudaStreamWaitEvent(s2, ev2, 0);
    k_mma1<128, 128><<<gemmBlocks, 256, SMEM_N128_1S, s2>>>(
        (const __nv_bfloat16*)p_Xh, (const __nv_bfloat16*)p_Xl,
        BRh, BRl, (float*)p_HGXR + 128, 256, n);
    cudaEventRecord(ev3, s2);                       // xr done

    // s0: agg needs attn scalars + fp16 x (s0) + CSR (s1)
    cudaStreamWaitEvent(0, ev1, 0);
    k_agg<<<warpBlocks, 256>>>(x, n);

    // gat + x2pre GEMMs fused into one launch (needs buildW)
    cudaStreamWaitEvent(0, evbw, 0);
    k_mma1d<128, 128><<<dim3(gemmBlocks, 2), 256, SMEM_N128_1S>>>(
        (const __nv_bfloat16*)p_AGh, (const __nv_bfloat16*)p_AGl, BGh, BGl, (float*)p_gat,
        (const __nv_bfloat16*)p_A1h, (const __nv_bfloat16*)p_A1l,
        (const __nv_bfloat16*)p_B2h, (const __nv_bfloat16*)p_B2l, (float*)p_x2pre, n);

    // join xr before LN1
    cudaStreamWaitEvent(0, ev3, 0);
    k_ln1<<<warpBlocks, 256>>>(bgat, b1l, ln1g, ln1b, n);
    k_sage2<<<warpBlocks, 256>>>(n);
    // G3 fused: h2pre GEMM + LN2 + classifier -> out
    k_g3fused<<<gemmBlocks, 256, SMEM_G3>>>(
        (const __nv_bfloat16*)p_AXh, (const __nv_bfloat16*)p_AXl,
        (const __nv_bfloat16*)p_B3h, (const __nv_bfloat16*)p_B3l,
        b2l, ln2g, ln2b, Wc, bc, out, n);
}

// round 17
// speedup vs baseline: 1.4764x; 1.4764x over previous
#include <cuda_runtime.h>
#include <cuda_fp16.h>
#include <cstdint>

// Problem constants (fixed by the dataset)
#define NMAX 50000
#define EMAX 800000
#define NPAD 50048   // NMAX rounded up to 128

// ---------------- scratch (static __device__ arrays; no allocations) -------
__device__ __align__(16) float g_HGXR[(size_t)NPAD * 256]; // [.. | xr]
__device__ __align__(16) float g_gat [(size_t)NPAD * 128]; // gpre = aggat @ Wgat
__device__ __align__(16) float g_x2pre[(size_t)NPAD * 128];
__device__ float g_as[NMAX];
__device__ float g_ad[NMAX];
__device__ float g_ws[128];
__device__ float g_wd[128];
__device__ int   g_cnt[NMAX];
__device__ int   g_rowptr[NMAX + 1];
__device__ int   g_cursor[NMAX];
__device__ int   g_col[EMAX];
__device__ int   g_bsum[64];
__device__ int   g_boff[64];
// fp16 GEMM operands
__device__ __align__(16) __half g_Xf [(size_t)NPAD * 128];  // x
__device__ __align__(16) __half g_A1f[(size_t)NPAD * 128];  // agg1
__device__ __align__(16) __half g_AGf[(size_t)NPAD * 128];  // alpha-agg x
__device__ __align__(16) __half g_AXf[(size_t)NPAD * 512];  // [agg2 | h] (h also sage2 payload)
// fp16 transposed weights: [N][K] K-major
__device__ __align__(16) __half g_B1f[256 * 128];  // [Wgat|W1r]^T
__device__ __align__(16) __half g_B2f[128 * 128];  // W1l^T
__device__ __align__(16) __half g_B3f[256 * 512];  // [W2l;W2r]^T

// ---------------- small helpers --------------------------------------------
__device__ __forceinline__ float lrelu(float x) { return x > 0.f ? x : 0.2f * x; }
__device__ __forceinline__ float4 f4zero() { return make_float4(0.f, 0.f, 0.f, 0.f); }
__device__ __forceinline__ float4 f4add(float4 a, float4 b) {
    return make_float4(a.x + b.x, a.y + b.y, a.z + b.z, a.w + b.w);
}
__device__ __forceinline__ float4 f4scale(float4 a, float s) {
    return make_float4(a.x * s, a.y * s, a.z * s, a.w * s);
}
__device__ __forceinline__ float4 f4fma(float s, float4 a, float4 acc) {
    acc.x = fmaf(s, a.x, acc.x); acc.y = fmaf(s, a.y, acc.y);
    acc.z = fmaf(s, a.z, acc.z); acc.w = fmaf(s, a.w, acc.w);
    return acc;
}
__device__ __forceinline__ uint32_t smem_u32(const void* p) {
    uint32_t a;
    asm("{ .reg .u64 t; cvta.to.shared.u64 t, %1; cvt.u32.u64 %0, t; }" : "=r"(a) : "l"(p));
    return a;
}
__device__ __forceinline__ uint32_t swz(uint32_t off) { return off ^ ((off >> 3) & 0x70); }
__device__ __forceinline__ uint32_t h2u(__half2 h) { return *(uint32_t*)&h; }

// ---------------- warp MMA primitives (sm_80+, legal on plain sm_103) -------
__device__ __forceinline__ void ldsm4(uint32_t* r, uint32_t addr) {
    asm volatile("ldmatrix.sync.aligned.m8n8.x4.shared.b16 {%0,%1,%2,%3}, [%4];"
                 : "=r"(r[0]), "=r"(r[1]), "=r"(r[2]), "=r"(r[3]) : "r"(addr));
}
__device__ __forceinline__ void mma16816f(float* d, const uint32_t* a, const uint32_t* b) {
    asm volatile(
        "mma.sync.aligned.m16n8k16.row.col.f32.f16.f16.f32 "
        "{%0,%1,%2,%3}, {%4,%5,%6,%7}, {%8,%9}, {%0,%1,%2,%3};"
        : "+f"(d[0]), "+f"(d[1]), "+f"(d[2]), "+f"(d[3])
        : "r"(a[0]), "r"(a[1]), "r"(a[2]), "r"(a[3]), "r"(b[0]), "r"(b[1]));
}
__device__ __forceinline__ void cpa16(uint32_t saddr, const void* gaddr) {
    asm volatile("cp.async.cg.shared.global [%0], [%1], 16;" :: "r"(saddr), "l"(gaddr));
}
__device__ __forceinline__ void cpa_commit() { asm volatile("cp.async.commit_group;"); }
__device__ __forceinline__ void cpa_wait0() { asm volatile("cp.async.wait_group 0;"); }

// ---------------- weight packing: transpose + fp16 ---------------------------
__global__ void k_buildW(const float* __restrict__ Wg, const float* __restrict__ W1r,
                         const float* __restrict__ W1l, const float* __restrict__ W2l,
                         const float* __restrict__ W2r) {
    int i = blockIdx.x * blockDim.x + threadIdx.x;
    if (i < 256 * 128) {
        int nn = i / 128, k = i % 128;
        float w = (nn < 128) ? Wg[k * 128 + nn] : W1r[k * 128 + (nn - 128)];
        g_B1f[i] = __float2half_rn(w);
    }
    if (i < 128 * 128) {
        int nn = i / 128, k = i % 128;
        g_B2f[i] = __float2half_rn(W1l[k * 128 + nn]);
    }
    if (i < 256 * 512) {
        int nn = i / 512, k = i % 512;
        float w = (k < 256) ? W2l[k * 256 + nn] : W2r[(k - 256) * 256 + nn];
        g_B3f[i] = __float2half_rn(w);
    }
}

// ---------------- ws = Wgat @ att_s, wd = Wgat @ att_d (warp per output) ----
__global__ void k_prew(const float* __restrict__ Wg, const float* __restrict__ att_s,
                       const float* __restrict__ att_d) {
    int k = (blockIdx.x * blockDim.x + threadIdx.x) >> 5;
    int lane = threadIdx.x & 31;
    if (k >= 128) return;
    float4 w = ((const float4*)(Wg + k * 128))[lane];
    float4 a = ((const float4*)att_s)[lane];
    float4 d = ((const float4*)att_d)[lane];
    float s = w.x * a.x + w.y * a.y + w.z * a.z + w.w * a.w;
    float t = w.x * d.x + w.y * d.y + w.z * d.z + w.w * d.w;
    for (int o = 16; o; o >>= 1) {
        s += __shfl_xor_sync(0xffffffffu, s, o);
        t += __shfl_xor_sync(0xffffffffu, t, o);
    }
    if (lane == 0) { g_ws[k] = s; g_wd[k] = t; }
}

// ---------------- x -> fp16 + attention scalars ------------------------------
__global__ void k_splitX(const float* __restrict__ x, int n) {
    int i = blockIdx.x * blockDim.x + threadIdx.x;   // float4 index over NPAD*32
    if (i >= NPAD * 32) return;
    int row = i >> 5;
    int lane = i & 31;
    float4 v = (row < n) ? ((const float4*)x)[i] : f4zero();
    ((uint2*)g_Xf)[i] = make_uint2(h2u(__floats2half2_rn(v.x, v.y)),
                                   h2u(__floats2half2_rn(v.z, v.w)));
    float4 a = ((const float4*)g_ws)[lane];
    float4 d = ((const float4*)g_wd)[lane];
    float s = v.x * a.x + v.y * a.y + v.z * a.z + v.w * a.w;
    float t = v.x * d.x + v.y * d.y + v.z * d.z + v.w * d.w;
    for (int o = 16; o; o >>= 1) {
        s += __shfl_xor_sync(0xffffffffu, s, o);
        t += __shfl_xor_sync(0xffffffffu, t, o);
    }
    if (lane == 0 && row < n) { g_as[row] = s; g_ad[row] = t; }
}

// ---------------- CSR build --------------------------------------------------
__global__ void k_deg(const int* __restrict__ ei, int E) {
    int e = blockIdx.x * blockDim.x + threadIdx.x;
    if (e < E) atomicAdd(&g_cnt[ei[E + e]], 1);
}

__global__ void k_blockscan(int n) {   // 1024 threads/block
    __shared__ int ws[32];
    int i = blockIdx.x * 1024 + threadIdx.x;
    int lane = threadIdx.x & 31, wid = threadIdx.x >> 5;
    int v = (i < n) ? g_cnt[i] : 0;
    int x = v;
#pragma unroll
    for (int o = 1; o < 32; o <<= 1) {
        int t = __shfl_up_sync(0xffffffffu, x, o);
        if (lane >= o) x += t;
    }
    if (lane == 31) ws[wid] = x;
    __syncthreads();
    if (wid == 0) {
        int s = ws[lane];
#pragma unroll
        for (int o = 1; o < 32; o <<= 1) {
            int t = __shfl_up_sync(0xffffffffu, s, o);
            if (lane >= o) s += t;
        }
        ws[lane] = s;
    }
    __syncthreads();
    int excl = x - v + (wid ? ws[wid - 1] : 0);
    if (i < n) g_rowptr[i] = excl;
    if (threadIdx.x == 1023) g_bsum[blockIdx.x] = excl + v;
}

__global__ void k_scantop(int nb, int n) {  // 64 threads, nb <= 64
    __shared__ int sh[64];
    int t = threadIdx.x;
    int v0 = (t < nb) ? g_bsum[t] : 0;
    sh[t] = v0;
    __syncthreads();
    for (int o = 1; o < 64; o <<= 1) {
        int v = (t >= o) ? sh[t - o] : 0;
        __syncthreads();
        sh[t] += v;
        __syncthreads();
    }
    if (t < nb) g_boff[t] = sh[t] - v0;
    if (t == 0) g_rowptr[n] = sh[63];
}

__global__ void k_addoff(int n) {
    int i = blockIdx.x * blockDim.x + threadIdx.x;
    if (i < n) {
        int val = g_rowptr[i] + g_boff[i >> 10];
        g_rowptr[i] = val;
        g_cursor[i] = val;
    }
}

__global__ void k_scatter(const int* __restrict__ ei, int E) {
    int e = blockIdx.x * blockDim.x + threadIdx.x;
    if (e < E) {
        int s = ei[e];
        int d = ei[E + e];
        int p = atomicAdd(&g_cursor[d], 1);
        g_col[p] = s;
    }
}

// ---------------- merged GAT + SAGE1 aggregation over fp32 x (warp/node) ----
__global__ void k_agg(const float* __restrict__ x, int n) {
    int w = (blockIdx.x * blockDim.x + threadIdx.x) >> 5;
    int lane = threadIdx.x & 31;
    if (w >= n) return;
    int base = g_rowptr[w];
    int deg = g_rowptr[w + 1] - base;
    float adi = g_ad[w];
    float eself = lrelu(g_as[w] + adi);
    float m = eself;
    for (int j = lane; j < deg; j += 32)
        m = fmaxf(m, lrelu(g_as[g_col[base + j]] + adi));
    for (int o = 16; o; o >>= 1) m = fmaxf(m, __shfl_xor_sync(0xffffffffu, m, o));

    float wself = __expf(eself - m);
    float ssum = wself;
    float4 xv = ((const float4*)(x + (size_t)w * 128))[lane];
    float4 ag = f4scale(xv, wself);
    float4 sg = f4zero();
    int j = 0;
    for (; j + 1 < deg; j += 2) {
        int s0 = g_col[base + j], s1 = g_col[base + j + 1];
        float w0 = __expf(lrelu(g_as[s0] + adi) - m);
        float w1 = __expf(lrelu(g_as[s1] + adi) - m);
        float4 v0 = ((const float4*)(x + (size_t)s0 * 128))[lane];
        float4 v1 = ((const float4*)(x + (size_t)s1 * 128))[lane];
        ssum += w0 + w1;
        ag = f4fma(w0, v0, ag);
        ag = f4fma(w1, v1, ag);
        sg = f4add(sg, v0);
        sg = f4add(sg, v1);
    }
    if (j < deg) {
        int s0 = g_col[base + j];
        float w0 = __expf(lrelu(g_as[s0] + adi) - m);
        float4 v0 = ((const float4*)(x + (size_t)s0 * 128))[lane];
        ssum += w0;
        ag = f4fma(w0, v0, ag);
        sg = f4add(sg, v0);
    }
    float ia = 1.f / ssum;
    float is = 1.f / fmaxf((float)deg, 1.f);
    ag = f4scale(ag, ia);
    sg = f4scale(sg, is);
    ((uint2*)(g_AGf + (size_t)w * 128))[lane] =
        make_uint2(h2u(__floats2half2_rn(ag.x, ag.y)), h2u(__floats2half2_rn(ag.z, ag.w)));
    ((uint2*)(g_A1f + (size_t)w * 128))[lane] =
        make_uint2(h2u(__floats2half2_rn(sg.x, sg.y)), h2u(__floats2half2_rn(sg.z, sg.w)));
}

// ---------------- fp16 mma.sync GEMM body, cp.async staged -------------------
// C[rows,NC] = A[rows,K] @ B[NC,K]^T, all operands fp16, fp32 accumulate.
template <int K, int NC, int STAGES>
__device__ __forceinline__ void mma_body(
        const __half* __restrict__ A, const __half* __restrict__ B,
        float* __restrict__ C, int ldc, int nrows) {
    constexpr int NCH = K / 64;
    constexpr int WN = NC / 4;
    constexpr int NF = WN / 8;
    constexpr int AB = 128 * 128;       // bytes: 128 rows x 64 fp16
    constexpr int BB = NC * 128;
    constexpr int STAGE = AB + BB;

    extern __shared__ char dsm[];
    uint32_t raw = smem_u32(dsm);
    uint32_t base = (raw + 1023u) & ~1023u;

    int tid = threadIdx.x;
    int lane = tid & 31, wid = tid >> 5;
    int wm0 = (wid >> 2) * 64;
    int wn0 = (wid & 3) * WN;
    int row0 = blockIdx.x * 128;

    float acc[4][NF][4];
#pragma unroll
    for (int mf = 0; mf < 4; mf++)
#pragma unroll
        for (int nf = 0; nf < NF; nf++)
#pragma unroll
            for (int q = 0; q < 4; q++) acc[mf][nf][q] = 0.f;

    int srow = tid >> 1;
    int half = tid & 1;
    const char* pA = (const char*)(A + (size_t)(row0 + srow) * K) + half * 64;
    uint32_t aoff = (uint32_t)srow * 128u + (uint32_t)half * 64u;

    auto issue = [&](int ch, int buf) {
        uint32_t sb = base + (uint32_t)buf * STAGE;
        int kb = ch * 128;
#pragma unroll
        for (int g = 0; g < 4; g++)
            cpa16(sb + swz(aoff + g * 16u), pA + kb + g * 16);
#pragma unroll
        for (int rr = 0; rr < NC / 128; rr++) {
            int nrow = srow + rr * 128;
            const char* pb = (const char*)(B + (size_t)nrow * K) + half * 64;
            uint32_t boff = (uint32_t)nrow * 128u + (uint32_t)half * 64u;
#pragma unroll
            for (int g = 0; g < 4; g++)
                cpa16(sb + AB + swz(boff + g * 16u), pb + kb + g * 16);
        }
        cpa_commit();
    };

    auto compute = [&](uint32_t sb) {
        uint32_t aA = sb, aB = sb + AB;
#pragma unroll
        for (int ks = 0; ks < 4; ks++) {
            uint32_t Af[4][4];
            uint32_t ar = (uint32_t)(wm0 + (lane & 15));
            uint32_t akb = (uint32_t)(ks * 16 + ((lane >> 4) * 8));
#pragma unroll
            for (int mf = 0; mf < 4; mf++)
                ldsm4(Af[mf], aA + swz((ar + mf * 16) * 128u + akb * 2u));
#pragma unroll
            for (int np = 0; np < NF / 2; np++) {
                uint32_t nr = (uint32_t)(wn0 + np * 16 + (lane & 7) + ((lane >> 4) & 1) * 8);
                uint32_t bkb = (uint32_t)(ks * 16 + ((lane >> 3) & 1) * 8);
                uint32_t Bf[4];
                ldsm4(Bf, aB + swz(nr * 128u + bkb * 2u));
#pragma unroll
                for (int mf = 0; mf < 4; mf++) {
#pragma unroll
                    for (int j = 0; j < 2; j++)
                        mma16816f(acc[mf][np * 2 + j], Af[mf], Bf + j * 2);
                }
            }
        }
    };

    if (STAGES == 2) {
        issue(0, 0);
        for (int ch = 0; ch < NCH; ch++) {
            cpa_wait0();
            __syncthreads();
            if (ch + 1 < NCH) issue(ch + 1, (ch + 1) & 1);
            compute(base + (uint32_t)(ch & 1) * STAGE);
            __syncthreads();
        }
    } else {
        for (int ch = 0; ch < NCH; ch++) {
            issue(ch, 0);
            cpa_wait0();
            __syncthreads();
            compute(base);
            __syncthreads();
        }
    }

#pragma unroll
    for (int mf = 0; mf < 4; mf++) {
        int r_ = row0 + wm0 + mf * 16 + (lane >> 2);
#pragma unroll
        for (int nf = 0; nf < NF; nf++) {
            int c = wn0 + nf * 8 + (lane & 3) * 2;
            if (r_ < nrows)
                *(float2*)(C + (size_t)r_ * ldc + c) = make_float2(acc[mf][nf][0], acc[mf][nf][1]);
            if (r_ + 8 < nrows)
                *(float2*)(C + (size_t)(r_ + 8) * ldc + c) = make_float2(acc[mf][nf][2], acc[mf][nf][3]);
        }
    }
}

// single-stage kernel (short K; 2 CTAs/SM via launch_bounds)
template <int K, int NC>
__global__ void __launch_bounds__(256, 2)
k_mma1(const __half* __restrict__ A, const __half* __restrict__ B,
       float* __restrict__ C, int ldc, int nrows) {
    mma_body<K, NC, 1>(A, B, C, ldc, nrows);
}

// dual-operand single-stage variant: blockIdx.y selects operand set
template <int K, int NC>
__global__ void __launch_bounds__(256, 2)
k_mma1d(const __half* __restrict__ A0, const __half* __restrict__ B0, float* __restrict__ C0,
        const __half* __restrict__ A1, const __half* __restrict__ B1, float* __restrict__ C1,
        int nrows) {
    if (blockIdx.y == 0)
        mma_body<K, NC, 1>(A0, B0, C0, NC, nrows);
    else
        mma_body<K, NC, 1>(A1, B1, C1, NC, nrows);
}

// ---------------- G3 fused: h2pre GEMM + LN2 + classifier dot ---------------
__global__ void __launch_bounds__(256)
k_g3fused(const __half* __restrict__ A, const __half* __restrict__ B,
          const float* __restrict__ b2l, const float* __restrict__ g2,
          const float* __restrict__ be2, const float* __restrict__ Wc,
          const float* __restrict__ bc, float* __restrict__ out, int nrows) {
    constexpr int K = 512, NC = 256;
    constexpr int NCH = K / 64;
    constexpr int NF = 8;               // WN=64
    constexpr int AB = 128 * 128;
    constexpr int BB = NC * 128;
    constexpr int STAGE = AB + BB;
    constexpr int SROW = 258;           // padded fp32 row stride

    extern __shared__ char dsm[];
    uint32_t raw = smem_u32(dsm);
    uint32_t base = (raw + 1023u) & ~1023u;

    int tid = threadIdx.x;
    int lane = tid & 31, wid = tid >> 5;
    int wm0 = (wid >> 2) * 64;
    int wn0 = (wid & 3) * 64;
    int row0 = blockIdx.x * 128;

    float acc[4][NF][4];
#pragma unroll
    for (int mf = 0; mf < 4; mf++)
#pragma unroll
        for (int nf = 0; nf < NF; nf++)
#pragma unroll
            for (int q = 0; q < 4; q++) acc[mf][nf][q] = 0.f;

    int srow = tid >> 1;
    int half = tid & 1;
    const char* pA = (const char*)(A + (size_t)(row0 + srow) * K) + half * 64;
    uint32_t aoff = (uint32_t)srow * 128u + (uint32_t)half * 64u;

    auto issue = [&](int ch, int buf) {
        uint32_t sb = base + (uint32_t)buf * STAGE;
        int kb = ch * 128;
#pragma unroll
        for (int g = 0; g < 4; g++)
            cpa16(sb + swz(aoff + g * 16u), pA + kb + g * 16);
#pragma unroll
        for (int rr = 0; rr < 2; rr++) {
            int nrow = srow + rr * 128;
            const char* pb = (const char*)(B + (size_t)nrow * K) + half * 64;
            uint32_t boff = (uint32_t)nrow * 128u + (uint32_t)half * 64u;
#pragma unroll
            for (int g = 0; g < 4; g++)
                cpa16(sb + AB + swz(boff + g * 16u), pb + kb + g * 16);
        }
        cpa_commit();
    };

    auto compute = [&](uint32_t sb) {
        uint32_t aA = sb, aB = sb + AB;
#pragma unroll
        for (int ks = 0; ks < 4; ks++) {
            uint32_t Af[4][4];
            uint32_t ar = (uint32_t)(wm0 + (lane & 15));
            uint32_t akb = (uint32_t)(ks * 16 + ((lane >> 4) * 8));
#pragma unroll
            for (int mf = 0; mf < 4; mf++)
                ldsm4(Af[mf], aA + swz((ar + mf * 16) * 128u + akb * 2u));
#pragma unroll
            for (int np = 0; np < NF / 2; np++) {
                uint32_t nr = (uint32_t)(wn0 + np * 16 + (lane & 7) + ((lane >> 4) & 1) * 8);
                uint32_t bkb = (uint32_t)(ks * 16 + ((lane >> 3) & 1) * 8);
                uint32_t Bf[4];
                ldsm4(Bf, aB + swz(nr * 128u + bkb * 2u));
#pragma unroll
                for (int mf = 0; mf < 4; mf++) {
#pragma unroll
                    for (int j = 0; j < 2; j++)
                        mma16816f(acc[mf][np * 2 + j], Af[mf], Bf + j * 2);
                }
            }
        }
    };

    issue(0, 0);
    for (int ch = 0; ch < NCH; ch++) {
        cpa_wait0();
        __syncthreads();
        if (ch + 1 < NCH) issue(ch + 1, (ch + 1) & 1);
        compute(base + (uint32_t)(ch & 1) * STAGE);
        __syncthreads();
    }

    // ---- fused epilogue: stage 128x256 fp32 tile in smem ----
    float* sC = (float*)(dsm + (base - raw));
#pragma unroll
    for (int mf = 0; mf < 4; mf++) {
        int r_ = wm0 + mf * 16 + (lane >> 2);
#pragma unroll
        for (int nf = 0; nf < NF; nf++) {
            int c = wn0 + nf * 8 + (lane & 3) * 2;
            *(float2*)(sC + r_ * SROW + c) = make_float2(acc[mf][nf][0], acc[mf][nf][1]);
            *(float2*)(sC + (r_ + 8) * SROW + c) = make_float2(acc[mf][nf][2], acc[mf][nf][3]);
        }
    }
    __syncthreads();

    float bc0 = bc[0];
    for (int rr = 0; rr < 16; rr++) {
        int r = wid * 16 + rr;
        int grow = row0 + r;
        float v[8];
        float s = 0.f, q = 0.f;
#pragma unroll
        for (int t = 0; t < 8; t++) {
            int c = lane + 32 * t;
            float val = sC[r * SROW + c] + b2l[c];
            v[t] = val;
            s += val;
            q += val * val;
        }
        for (int o = 16; o; o >>= 1) {
            s += __shfl_xor_sync(0xffffffffu, s, o);
            q += __shfl_xor_sync(0xffffffffu, q, o);
        }
        float mu = s * (1.f / 256.f);
        float var = fmaxf(q * (1.f / 256.f) - mu * mu, 0.f);
        float rs = rsqrtf(var + 1e-5f);
        float a2 = 0.f;
#pragma unroll
        for (int t = 0; t < 8; t++) {
            int c = lane + 32 * t;
            float y = (v[t] - mu) * rs * g2[c] + be2[c];
            y = fmaxf(y, 0.f);
            a2 = fmaf(y, Wc[c], a2);
        }
        for (int o = 16; o; o >>= 1) a2 += __shfl_xor_sync(0xffffffffu, a2, o);
        if (lane == 0 && grow < nrows) out[grow] = a2 + bc0;
    }
}

// ---------------- LN1: h = relu(LN(...)) -> fp16 AX[:,256:] -----------------
__global__ void k_ln1(const float* __restrict__ bgat, const float* __restrict__ b1l,
                      const float* __restrict__ g1, const float* __restrict__ be1, int n) {
    int w = (blockIdx.x * blockDim.x + threadIdx.x) >> 5;
    int lane = threadIdx.x & 31;
    if (w >= n) return;
    float v[8];
    if (lane < 16) {
        int j0 = lane * 8;
        const float4* p = (const float4*)(g_gat + (size_t)w * 128 + j0);
        const float4* pb = (const float4*)(bgat + j0);
        float4 a = p[0], b = p[1], ab = pb[0], bb = pb[1];
        v[0] = a.x + ab.x; v[1] = a.y + ab.y; v[2] = a.z + ab.z; v[3] = a.w + ab.w;
        v[4] = b.x + bb.x; v[5] = b.y + bb.y; v[6] = b.z + bb.z; v[7] = b.w + bb.w;
    } else {
        int j0 = (lane - 16) * 8;
        const float4* p1 = (const float4*)(g_x2pre + (size_t)w * 128 + j0);
        const float4* p2 = (const float4*)(g_HGXR + (size_t)w * 256 + 128 + j0);
        const float4* pb = (const float4*)(b1l + j0);
        float4 a1 = p1[0], a2 = p2[0], ab = pb[0];
        float4 c1 = p1[1], c2 = p2[1], cb = pb[1];
        v[0] = a1.x + a2.x + ab.x; v[1] = a1.y + a2.y + ab.y;
        v[2] = a1.z + a2.z + ab.z; v[3] = a1.w + a2.w + ab.w;
        v[4] = c1.x + c2.x + cb.x; v[5] = c1.y + c2.y + cb.y;
        v[6] = c1.z + c2.z + cb.z; v[7] = c1.w + c2.w + cb.w;
    }
    float s = 0.f, q = 0.f;
#pragma unroll
    for (int t = 0; t < 8; t++) { s += v[t]; q += v[t] * v[t]; }
    for (int o = 16; o; o >>= 1) {
        s += __shfl_xor_sync(0xffffffffu, s, o);
        q += __shfl_xor_sync(0xffffffffu, q, o);
    }
    float mu = s * (1.f / 256.f);
    float var = fmaxf(q * (1.f / 256.f) - mu * mu, 0.f);
    float rs = rsqrtf(var + 1e-5f);
    int c0 = lane * 8;
    float o[8];
#pragma unroll
    for (int t = 0; t < 8; t++) {
        float y = (v[t] - mu) * rs * g1[c0 + t] + be1[c0 + t];
        o[t] = fmaxf(y, 0.f);
    }
    uint4 P;
    P.x = h2u(__floats2half2_rn(o[0], o[1]));
    P.y = h2u(__floats2half2_rn(o[2], o[3]));
    P.z = h2u(__floats2half2_rn(o[4], o[5]));
    P.w = h2u(__floats2half2_rn(o[6], o[7]));
    *(uint4*)(g_AXf + (size_t)w * 512 + 256 + c0) = P;
}

// ---------------- SAGE2: mean of fp16 h -> fp16 AX[:,0:256] -----------------
__global__ void k_sage2(int n) {
    int w = (blockIdx.x * blockDim.x + threadIdx.x) >> 5;
    int lane = threadIdx.x & 31;
    if (w >= n) return;
    int base = g_rowptr[w];
    int deg = g_rowptr[w + 1] - base;
    float acc[8];
#pragma unroll
    for (int t = 0; t < 8; t++) acc[t] = 0.f;
    int c0 = lane * 8;
    int j = 0;
    for (; j + 1 < deg; j += 2) {
        int s0 = g_col[base + j], s1 = g_col[base + j + 1];
        uint4 P0 = *(const uint4*)(g_AXf + (size_t)s0 * 512 + 256 + c0);
        uint4 P1 = *(const uint4*)(g_AXf + (size_t)s1 * 512 + 256 + c0);
        float2 f;
        f = __half22float2(*(__half2*)&P0.x); acc[0] += f.x; acc[1] += f.y;
        f = __half22float2(*(__half2*)&P0.y); acc[2] += f.x; acc[3] += f.y;
        f = __half22float2(*(__half2*)&P0.z); acc[4] += f.x; acc[5] += f.y;
        f = __half22float2(*(__half2*)&P0.w); acc[6] += f.x; acc[7] += f.y;
        f = __half22float2(*(__half2*)&P1.x); acc[0] += f.x; acc[1] += f.y;
        f = __half22float2(*(__half2*)&P1.y); acc[2] += f.x; acc[3] += f.y;
        f = __half22float2(*(__half2*)&P1.z); acc[4] += f.x; acc[5] += f.y;
        f = __half22float2(*(__half2*)&P1.w); acc[6] += f.x; acc[7] += f.y;
    }
    if (j < deg) {
        int s0 = g_col[base + j];
        uint4 P = *(const uint4*)(g_AXf + (size_t)s0 * 512 + 256 + c0);
        float2 f;
        f = __half22float2(*(__half2*)&P.x); acc[0] += f.x; acc[1] += f.y;
        f = __half22float2(*(__half2*)&P.y); acc[2] += f.x; acc[3] += f.y;
        f = __half22float2(*(__half2*)&P.z); acc[4] += f.x; acc[5] += f.y;
        f = __half22float2(*(__half2*)&P.w); acc[6] += f.x; acc[7] += f.y;
    }
    float inv = 1.f / fmaxf((float)deg, 1.f);
#pragma unroll
    for (int t = 0; t < 8; t++) acc[t] *= inv;
    uint4 P;
    P.x = h2u(__floats2half2_rn(acc[0], acc[1]));
    P.y = h2u(__floats2half2_rn(acc[2], acc[3]));
    P.z = h2u(__floats2half2_rn(acc[4], acc[5]));
    P.w = h2u(__floats2half2_rn(acc[6], acc[7]));
    *(uint4*)(g_AXf + (size_t)w * 512 + c0) = P;
}

// ---------------- launch ----------------------------------------------------
extern "C" void kernel_launch(void* const* d_in, const int* in_sizes, int n_in,
                              void* d_out, int out_size) {
    const float* x      = (const float*)d_in[0];
    const int*   ei     = (const int*)d_in[1];     // int32 (JAX x64 disabled)
    const float* Wg     = (const float*)d_in[2];
    const float* att_s  = (const float*)d_in[3];
    const float* att_d  = (const float*)d_in[4];
    const float* bgat   = (const float*)d_in[5];
    const float* W1l    = (const float*)d_in[6];
    const float* b1l    = (const float*)d_in[7];
    const float* W1r    = (const float*)d_in[8];
    const float* ln1g   = (const float*)d_in[9];
    const float* ln1b   = (const float*)d_in[10];
    const float* W2l    = (const float*)d_in[11];
    const float* b2l    = (const float*)d_in[12];
    const float* W2r    = (const float*)d_in[13];
    const float* ln2g   = (const float*)d_in[14];
    const float* ln2b   = (const float*)d_in[15];
    const float* Wc     = (const float*)d_in[16];
    const float* bc     = (const float*)d_in[17];
    float* out = (float*)d_out;

    int n = in_sizes[0] / 128;
    int E = in_sizes[1] / 2;

    void *p_HGXR, *p_gat, *p_x2pre, *p_cnt;
    void *p_Xf, *p_A1f, *p_AGf, *p_AXf, *p_B1f, *p_B2f, *p_B3f;
    cudaGetSymbolAddress(&p_HGXR, g_HGXR);
    cudaGetSymbolAddress(&p_gat, g_gat);
    cudaGetSymbolAddress(&p_x2pre, g_x2pre);
    cudaGetSymbolAddress(&p_cnt, g_cnt);
    cudaGetSymbolAddress(&p_Xf, g_Xf);
    cudaGetSymbolAddress(&p_A1f, g_A1f);
    cudaGetSymbolAddress(&p_AGf, g_AGf);
    cudaGetSymbolAddress(&p_AXf, g_AXf);
    cudaGetSymbolAddress(&p_B1f, g_B1f);
    cudaGetSymbolAddress(&p_B2f, g_B2f);
    cudaGetSymbolAddress(&p_B3f, g_B3f);

    // smem: fp16 single-operand tiles
    const int SMEM_128 = (16384 + 16384) + 1024;                  // 33792 (1-stage, NC=128)
    const int SMEM_G3  = 128 * 258 * 4 + 1024;                    // 133120 (epilogue-dominated)
    cudaFuncSetAttribute(k_mma1<128, 128>, cudaFuncAttributeMaxDynamicSharedMemorySize, SMEM_128);
    cudaFuncSetAttribute(k_mma1d<128, 128>, cudaFuncAttributeMaxDynamicSharedMemorySize, SMEM_128);
    cudaFuncSetAttribute(k_g3fused, cudaFuncAttributeMaxDynamicSharedMemorySize, SMEM_G3);

    // streams/events for capture-time DAG parallelism (created once; no device mem)
    static cudaStream_t s1 = 0, s2 = 0;
    static cudaEvent_t ev0, ev1, ev2, ev3, evbw;
    if (!s1) {
        cudaStreamCreateWithFlags(&s1, cudaStreamNonBlocking);
        cudaStreamCreateWithFlags(&s2, cudaStreamNonBlocking);
        cudaEventCreateWithFlags(&ev0, cudaEventDisableTiming);
        cudaEventCreateWithFlags(&ev1, cudaEventDisableTiming);
        cudaEventCreateWithFlags(&ev2, cudaEventDisableTiming);
        cudaEventCreateWithFlags(&ev3, cudaEventDisableTiming);
        cudaEventCreateWithFlags(&evbw, cudaEventDisableTiming);
    }

    int warpBlocks = (n + 7) / 8;       // 256 threads = 8 warps, warp-per-node
    int gemmBlocks = (n + 127) / 128;
    int nb = (n + 1023) / 1024;

    const __half* BG = (const __half*)p_B1f;              // Wgat^T rows 0..127
    const __half* BR = (const __half*)p_B1f + 128 * 128;  // W1r^T rows 128..255

    // ---- fork points ----
    cudaEventRecord(ev0, 0);

    // s1: CSR chain (depends only on ei)
    cudaStreamWaitEvent(s1, ev0, 0);
    cudaMemsetAsync(p_cnt, 0, (size_t)n * sizeof(int), s1);
    k_deg<<<(E + 255) / 256, 256, 0, s1>>>(ei, E);
    k_blockscan<<<nb, 1024, 0, s1>>>(n);
    k_scantop<<<1, 64, 0, s1>>>(nb, n);
    k_addoff<<<(n + 255) / 256, 256, 0, s1>>>(n);
    k_scatter<<<(E + 255) / 256, 256, 0, s1>>>(ei, E);
    cudaEventRecord(ev1, s1);                       // CSR done

    // s2: buildW (depends only on weights), later xr GEMM
    cudaStreamWaitEvent(s2, ev0, 0);
    k_buildW<<<512, 256, 0, s2>>>(Wg, W1r, W1l, W2l, W2r);
    cudaEventRecord(evbw, s2);                      // weights fp16 done

    // s0: prew -> splitX (fp16 x + attn scalars)
    k_prew<<<16, 256>>>(Wg, att_s, att_d);
    k_splitX<<<(NPAD * 32 + 255) / 256, 256>>>(x, n);
    cudaEventRecord(ev2, 0);                        // splitX done

    // s2: xr = x @ W1r -> HGXR[:,128:256] (after buildW [stream order] + splitX)
    cudaStreamWaitEvent(s2, ev2, 0);
    k_mma1<128, 128><<<gemmBlocks, 256, SMEM_128, s2>>>(
        (const __half*)p_Xf, BR, (float*)p_HGXR + 128, 256, n);
    cudaEventRecord(ev3, s2);                       // xr done

    // s0: agg needs attn scalars (s0) + CSR (s1)
    cudaStreamWaitEvent(0, ev1, 0);
    k_agg<<<warpBlocks, 256>>>(x, n);

    // gat + x2pre GEMMs fused into one launch (needs buildW)
    cudaStreamWaitEvent(0, evbw, 0);
    k_mma1d<128, 128><<<dim3(gemmBlocks, 2), 256, SMEM_128>>>(
        (const __half*)p_AGf, BG, (float*)p_gat,
        (const __half*)p_A1f, (const __half*)p_B2f, (float*)p_x2pre, n);

    // join xr before LN1
    cudaStreamWaitEvent(0, ev3, 0);
    k_ln1<<<warpBlocks, 256>>>(bgat, b1l, ln1g, ln1b, n);
    k_sage2<<<warpBlocks, 256>>>(n);
    // G3 fused: h2pre GEMM + LN2 + classifier -> out
    k_g3fused<<<gemmBlocks, 256, SMEM_G3>>>(
        (const __half*)p_AXf, (const __half*)p_B3f,
        b2l, ln2g, ln2b, Wc, bc, out, n);
}